// round 15
// baseline (speedup 1.0000x reference)
#include <cuda_runtime.h>
#include <math.h>
#include <stdint.h>

#define B_ 64
#define T_ 512
#define I_ 128
#define H_ 256
#define G_ 1024   // 4*H
#define C_ 3

#define NGROUP 16   // batch groups (= clusters)
#define BPG 4       // batches per group
#define RPG 8       // CTAs per group (= cluster size)
#define JPR 32      // j-values per CTA (H / RPG)

// ---------------- scratch (device globals; no allocation allowed) ----------
__device__ float d_G0[B_ * T_ * G_];     // gates_x layer 0
__device__ float d_G1[B_ * T_ * G_];     // gates_x layer 1
__device__ float d_H0[B_ * T_ * H_];     // h outputs layer 0
__device__ float d_HL[B_ * H_];          // last h of layer 1

// ---------------------------------------------------------------------------
// small PTX helpers
// ---------------------------------------------------------------------------
__device__ __forceinline__ uint32_t smem_u32(const void* p) {
    uint32_t a;
    asm("{ .reg .u64 t; cvta.to.shared.u64 t, %1; cvt.u32.u64 %0, t; }"
        : "=r"(a) : "l"(p));
    return a;
}
__device__ __forceinline__ float sigmf(float x) {
    return 1.f / (1.f + __expf(-x));
}
__device__ __forceinline__ float tanhff(float x) {
    return 2.f / (1.f + __expf(-2.f * x)) - 1.f;
}

#define MBAR_INIT(a, n) \
    asm volatile("mbarrier.init.shared.b64 [%0], %1;" :: "r"(a), "r"((uint32_t)(n)) : "memory")
#define MBAR_EXPECT(a, bytes) \
    asm volatile("mbarrier.arrive.expect_tx.shared.b64 _, [%0], %1;" :: "r"(a), "r"((uint32_t)(bytes)) : "memory")
#define MBAR_WAIT(a, par) do {                                                        \
    asm volatile("{\n\t.reg .pred P;\n"                                               \
        "WL%=: mbarrier.try_wait.parity.acquire.cta.shared::cta.b64 P, [%0], %1, 0x989680;\n\t" \
        "@P bra WD%=;\n\t bra WL%=;\nWD%=:\n\t}"                                      \
        :: "r"(a), "r"((uint32_t)(par)) : "memory");                                  \
} while (0)

// ---------------------------------------------------------------------------
// GEMM (NT): C[m][n] = sum_k A[m*K+k] * Bw[n*K+k] + bias1[n] + bias2[n]
// ---------------------------------------------------------------------------
__global__ void __launch_bounds__(256) gemm_nt_bias(
    const float* __restrict__ A, const float* __restrict__ Bw,
    const float* __restrict__ bias1, const float* __restrict__ bias2,
    float* __restrict__ C, int M, int N, int K)
{
    __shared__ float As[8][128];
    __shared__ float Bs[8][128];
    const int tid = threadIdx.x;
    const int m0 = blockIdx.y << 7;
    const int n0 = blockIdx.x << 7;
    const int ty = tid >> 4;
    const int tx = tid & 15;

    float acc[8][8];
#pragma unroll
    for (int i = 0; i < 8; i++)
#pragma unroll
        for (int j = 0; j < 8; j++) acc[i][j] = 0.f;

    const int lr = tid >> 1;
    const int lq = (tid & 1) << 2;

    for (int kt = 0; kt < K; kt += 8) {
        float4 va = *(const float4*)&A [(size_t)(m0 + lr) * K + kt + lq];
        float4 vb = *(const float4*)&Bw[(size_t)(n0 + lr) * K + kt + lq];
        As[lq + 0][lr] = va.x; As[lq + 1][lr] = va.y;
        As[lq + 2][lr] = va.z; As[lq + 3][lr] = va.w;
        Bs[lq + 0][lr] = vb.x; Bs[lq + 1][lr] = vb.y;
        Bs[lq + 2][lr] = vb.z; Bs[lq + 3][lr] = vb.w;
        __syncthreads();
#pragma unroll
        for (int kk = 0; kk < 8; kk++) {
            float ra[8], rb[8];
            *(float4*)&ra[0] = *(const float4*)&As[kk][ty * 8];
            *(float4*)&ra[4] = *(const float4*)&As[kk][ty * 8 + 4];
            *(float4*)&rb[0] = *(const float4*)&Bs[kk][tx * 8];
            *(float4*)&rb[4] = *(const float4*)&Bs[kk][tx * 8 + 4];
#pragma unroll
            for (int i = 0; i < 8; i++)
#pragma unroll
                for (int j = 0; j < 8; j++)
                    acc[i][j] = fmaf(ra[i], rb[j], acc[i][j]);
        }
        __syncthreads();
    }

    float bb[8];
#pragma unroll
    for (int j = 0; j < 8; j++)
        bb[j] = bias1[n0 + tx * 8 + j] + bias2[n0 + tx * 8 + j];
#pragma unroll
    for (int i = 0; i < 8; i++) {
        float4 o0 = make_float4(acc[i][0] + bb[0], acc[i][1] + bb[1],
                                acc[i][2] + bb[2], acc[i][3] + bb[3]);
        float4 o1 = make_float4(acc[i][4] + bb[4], acc[i][5] + bb[5],
                                acc[i][6] + bb[6], acc[i][7] + bb[7]);
        size_t row = (size_t)(m0 + ty * 8 + i) * N + n0 + tx * 8;
        *(float4*)&C[row]     = o0;
        *(float4*)&C[row + 4] = o1;
    }
}

// ---------------------------------------------------------------------------
// Persistent LSTM scan, cluster version.
// 16 clusters x 8 CTAs x 256 threads. CTA rank r owns gate columns
// {gate*256 + r*32 .. +32}. h exchanged via DSMEM bulk copies with
// mbarrier complete_tx (double-buffered). W_hh slice (128KB) in SMEM.
//
// Dynamic SMEM layout (floats):
//   Wsh [0, 32768)  | hbuf [32768, 32768+2048) (2 x 1024) | red (+4096)
//   then 2 mbarriers (16 bytes).
// ---------------------------------------------------------------------------
#define HBUF_OFFB (32768u * 4u)
#define MBAR_OFFB ((32768u + 2048u + 4096u) * 4u)
#define SCAN_SMEM ((32768 + 2048 + 4096) * 4 + 16)
#define TX_BYTES  ((RPG - 1) * BPG * JPR * 4)   // 3584

__global__ void __launch_bounds__(256, 1) __cluster_dims__(RPG, 1, 1)
lstm_scan(const float* __restrict__ Gx, const float* __restrict__ Whh,
          float* __restrict__ h_all, float* __restrict__ h_last)
{
    extern __shared__ float sm[];
    float* Wsh  = sm;                    // [256][128] k-major
    float* hbuf = sm + 32768;            // [2][4][256]
    float* red  = hbuf + 2048;           // [8][512]

    const uint32_t smbase = smem_u32(sm);
    const int tid = threadIdx.x;
    uint32_t rank;
    asm("mov.u32 %0, %%cluster_ctarank;" : "=r"(rank));
    const int g  = blockIdx.x >> 3;
    const int j0 = (int)rank * JPR;
    const int b0 = g * BPG;

    // ---- load W_hh slice into SMEM (k-major, conflict-free LDS.128) ----
    {
        const int c    = tid & 127;
        const int half = tid >> 7;
        const int gate = c >> 5, jj = c & 31;
        const int gcol = gate * 256 + j0 + jj;
        const float* wrow = Whh + (size_t)gcol * H_ + half * 128;
#pragma unroll 4
        for (int kk = 0; kk < 128; kk += 4) {
            float4 v = *(const float4*)&wrow[kk];
            int k = half * 128 + kk;
            Wsh[(k + 0) * 128 + c] = v.x;
            Wsh[(k + 1) * 128 + c] = v.y;
            Wsh[(k + 2) * 128 + c] = v.z;
            Wsh[(k + 3) * 128 + c] = v.w;
        }
    }
    for (int i = tid; i < 2048; i += 256) hbuf[i] = 0.f;   // h_{-1} = 0

    if (tid == 0) {
        MBAR_INIT(smbase + MBAR_OFFB, 1);
        MBAR_INIT(smbase + MBAR_OFFB + 8, 1);
        MBAR_EXPECT(smbase + MBAR_OFFB,     TX_BYTES);
        MBAR_EXPECT(smbase + MBAR_OFFB + 8, TX_BYTES);
    }
    __syncthreads();
    // all mbarriers live before any peer can write into us
    asm volatile("barrier.cluster.arrive.aligned;" ::: "memory");
    asm volatile("barrier.cluster.wait.aligned;"   ::: "memory");

    const int cg = tid & 31;            // column group (4 cols)
    const int kc = tid >> 5;            // k chunk (32 k)  [== batch idx for act threads]
    const int jj = tid & 31;
    float cst = 0.f;

    // copy-issuer precompute: tid<28 sends (peer rr, batch cb) 128B chunk
    uint32_t peer_base = 0, cp_off = 0;
    if (tid < 28) {
        int rr = tid >> 2;
        rr += (rr >= (int)rank) ? 1 : 0;
        int cb = tid & 3;
        asm("mapa.shared::cluster.u32 %0, %1, %2;"
            : "=r"(peer_base) : "r"(smbase), "r"((uint32_t)rr));
        cp_off = (uint32_t)(cb * 256 + j0) * 4u;
    }

    const float* gxp = (tid < 128)
        ? Gx + ((size_t)(b0 + kc) * T_) * G_ + j0 + jj : Gx;

    for (int t = 0; t < T_; t++) {
        // prefetch gates_x (latency hidden under GEMM)
        float gx0 = 0.f, gx1 = 0.f, gx2 = 0.f, gx3 = 0.f;
        if (tid < 128) {
            const float* gp = gxp + (size_t)t * G_;
            gx0 = __ldg(gp);       gx1 = __ldg(gp + 256);
            gx2 = __ldg(gp + 512); gx3 = __ldg(gp + 768);
        }

        // ---- partial GEMM over k chunk kc ----
        float acc[4][4];
#pragma unroll
        for (int b = 0; b < 4; b++)
#pragma unroll
            for (int i = 0; i < 4; i++) acc[b][i] = 0.f;

        const float* wk = Wsh + (kc * 32) * 128 + cg * 4;
        const float* hp = hbuf + ((t + 1) & 1) * 1024 + kc * 32;
#pragma unroll 8
        for (int k = 0; k < 32; k++) {
            float4 w = *(const float4*)(wk + k * 128);
            float h0v = hp[k], h1v = hp[256 + k];
            float h2v = hp[512 + k], h3v = hp[768 + k];
            acc[0][0] = fmaf(w.x, h0v, acc[0][0]);
            acc[0][1] = fmaf(w.y, h0v, acc[0][1]);
            acc[0][2] = fmaf(w.z, h0v, acc[0][2]);
            acc[0][3] = fmaf(w.w, h0v, acc[0][3]);
            acc[1][0] = fmaf(w.x, h1v, acc[1][0]);
            acc[1][1] = fmaf(w.y, h1v, acc[1][1]);
            acc[1][2] = fmaf(w.z, h1v, acc[1][2]);
            acc[1][3] = fmaf(w.w, h1v, acc[1][3]);
            acc[2][0] = fmaf(w.x, h2v, acc[2][0]);
            acc[2][1] = fmaf(w.y, h2v, acc[2][1]);
            acc[2][2] = fmaf(w.z, h2v, acc[2][2]);
            acc[2][3] = fmaf(w.w, h2v, acc[2][3]);
            acc[3][0] = fmaf(w.x, h3v, acc[3][0]);
            acc[3][1] = fmaf(w.y, h3v, acc[3][1]);
            acc[3][2] = fmaf(w.z, h3v, acc[3][2]);
            acc[3][3] = fmaf(w.w, h3v, acc[3][3]);
        }
#pragma unroll
        for (int b = 0; b < 4; b++)
#pragma unroll
            for (int i = 0; i < 4; i++)
                red[kc * 512 + b * 128 + cg * 4 + i] = acc[b][i];
        __syncthreads();

        // ---- fused reduce + activation + local h store (128 threads) ----
        if (tid < 128) {
            const int base = kc * 128 + jj;   // kc == batch here
            float s0 = 0.f, s1 = 0.f, s2 = 0.f, s3 = 0.f;
#pragma unroll
            for (int p = 0; p < 8; p++) {
                s0 += red[p * 512 + base];
                s1 += red[p * 512 + base + 32];
                s2 += red[p * 512 + base + 64];
                s3 += red[p * 512 + base + 96];
            }
            float iv = sigmf(s0 + gx0);
            float fv = sigmf(s1 + gx1);
            float gv = tanhff(s2 + gx2);
            float ov = sigmf(s3 + gx3);
            cst = fv * cst + iv * gv;
            float hv = ov * tanhff(cst);

            hbuf[(t & 1) * 1024 + kc * 256 + j0 + jj] = hv;   // own slice
            if (h_all)
                h_all[((size_t)(b0 + kc) * T_ + t) * H_ + j0 + jj] = hv;
            if (h_last && t == T_ - 1)
                h_last[(b0 + kc) * H_ + j0 + jj] = hv;
        }
        __syncthreads();

        if (t < T_ - 1) {
            const uint32_t boff = (uint32_t)(t & 1) * 4096u;
            if (tid < 28) {
                // order generic STS (all act threads, post-bar) before async read
                asm volatile("fence.proxy.async.shared::cta;" ::: "memory");
                uint32_t src = smbase    + HBUF_OFFB + boff + cp_off;
                uint32_t dst = peer_base + HBUF_OFFB + boff + cp_off;
                uint32_t rmb = peer_base + MBAR_OFFB + (uint32_t)(t & 1) * 8u;
                asm volatile(
                    "cp.async.bulk.shared::cluster.shared::cta.mbarrier::complete_tx::bytes "
                    "[%0], [%1], %2, [%3];"
                    :: "r"(dst), "r"(src), "r"(128u), "r"(rmb) : "memory");
            }
            const uint32_t mb = smbase + MBAR_OFFB + (uint32_t)(t & 1) * 8u;
            MBAR_WAIT(mb, (t >> 1) & 1);
            if (tid == 0) MBAR_EXPECT(mb, TX_BYTES);   // re-arm for t+2
        }
    }

    // no CTA exits while peers could still address its SMEM
    asm volatile("barrier.cluster.arrive.aligned;" ::: "memory");
    asm volatile("barrier.cluster.wait.aligned;"   ::: "memory");
}

// ---------------------------------------------------------------------------
// Head: logits = h_last @ fc_w^T + fc_b ; softmax rows. One block.
// ---------------------------------------------------------------------------
__global__ void __launch_bounds__(192) head_kernel(
    const float* __restrict__ hl, const float* __restrict__ fw,
    const float* __restrict__ fb, float* __restrict__ out)
{
    __shared__ float lg[B_ * C_];
    const int tid = threadIdx.x;
    if (tid < B_ * C_) {
        const int b = tid / C_, c = tid % C_;
        float s = fb[c];
        const float* hr = hl + b * H_;
        const float* wr = fw + c * H_;
#pragma unroll 8
        for (int j = 0; j < H_; j++) s = fmaf(hr[j], wr[j], s);
        lg[tid] = s;
    }
    __syncthreads();
    if (tid < B_) {
        float a = lg[tid * 3], b2 = lg[tid * 3 + 1], c2 = lg[tid * 3 + 2];
        float m = fmaxf(a, fmaxf(b2, c2));
        float e0 = expf(a - m), e1 = expf(b2 - m), e2 = expf(c2 - m);
        float inv = 1.f / (e0 + e1 + e2);
        out[tid * 3]     = e0 * inv;
        out[tid * 3 + 1] = e1 * inv;
        out[tid * 3 + 2] = e2 * inv;
    }
}

// ---------------------------------------------------------------------------
extern "C" void kernel_launch(void* const* d_in, const int* in_sizes, int n_in,
                              void* d_out, int out_size)
{
    const float* x    = (const float*)d_in[0];
    const float* Wih0 = (const float*)d_in[1];
    const float* Whh0 = (const float*)d_in[2];
    const float* bih0 = (const float*)d_in[3];
    const float* bhh0 = (const float*)d_in[4];
    const float* Wih1 = (const float*)d_in[5];
    const float* Whh1 = (const float*)d_in[6];
    const float* bih1 = (const float*)d_in[7];
    const float* bhh1 = (const float*)d_in[8];
    const float* fw   = (const float*)d_in[9];
    const float* fb   = (const float*)d_in[10];
    float* out = (float*)d_out;

    float *G0, *G1, *H0, *HL;
    cudaGetSymbolAddress((void**)&G0, d_G0);
    cudaGetSymbolAddress((void**)&G1, d_G1);
    cudaGetSymbolAddress((void**)&H0, d_H0);
    cudaGetSymbolAddress((void**)&HL, d_HL);

    cudaFuncSetAttribute(lstm_scan, cudaFuncAttributeMaxDynamicSharedMemorySize,
                         SCAN_SMEM);

    const int M = B_ * T_;
    dim3 ggrid(G_ / 128, M / 128);

    // layer 0: gates_x0 = x @ W_ih_0^T + b
    gemm_nt_bias<<<ggrid, 256>>>(x, Wih0, bih0, bhh0, G0, M, G_, I_);
    // layer 0 recurrence -> full h0
    lstm_scan<<<NGROUP * RPG, 256, SCAN_SMEM>>>(G0, Whh0, H0, nullptr);
    // layer 1: gates_x1 = h0 @ W_ih_1^T + b
    gemm_nt_bias<<<ggrid, 256>>>(H0, Wih1, bih1, bhh1, G1, M, G_, H_);
    // layer 1 recurrence -> last h only
    lstm_scan<<<NGROUP * RPG, 256, SCAN_SMEM>>>(G1, Whh1, nullptr, HL);
    // FC + softmax
    head_kernel<<<1, 192>>>(HL, fw, fb, out);
}

// round 16
// speedup vs baseline: 1.4252x; 1.4252x over previous
#include <cuda_runtime.h>
#include <math.h>
#include <stdint.h>

#define B_ 64
#define T_ 512
#define I_ 128
#define H_ 256
#define G_ 1024   // 4*H
#define C_ 3

#define NGROUP 16   // batch groups
#define BPG 4       // batches per group
#define RPG 8       // CTAs per group
#define JPR 32      // j-values per CTA (H / RPG)

// ---------------- scratch (device globals; no allocation allowed) ----------
__device__ float d_G0[B_ * T_ * G_];       // gates_x layer 0
__device__ float d_G1[B_ * T_ * G_];       // gates_x layer 1
__device__ float d_H0[B_ * T_ * H_];       // h outputs layer 0
__device__ float d_HL[B_ * H_];            // last h of layer 1
__device__ float d_hx[2][B_ * H_];         // h exchange, double buffered
__device__ unsigned int d_bar2[2][NGROUP]; // monotonic per-parity step counters
__device__ int          d_done[NGROUP];    // exit handshake for reset

// ---------------------------------------------------------------------------
// helpers
// ---------------------------------------------------------------------------
__device__ __forceinline__ void fma2(unsigned long long& d,
                                     unsigned long long a,
                                     unsigned long long b) {
    asm("fma.rn.f32x2 %0, %1, %2, %0;" : "+l"(d) : "l"(a), "l"(b));
}
__device__ __forceinline__ float pair_sum(unsigned long long p) {
    float lo, hi;
    asm("mov.b64 {%0, %1}, %2;" : "=f"(lo), "=f"(hi) : "l"(p));
    return lo + hi;
}
__device__ __forceinline__ float sigmf(float x) {
    return 1.f / (1.f + __expf(-x));
}
__device__ __forceinline__ float tanhff(float x) {
    return 2.f / (1.f + __expf(-2.f * x)) - 1.f;
}

// ---------------------------------------------------------------------------
// GEMM (NT): C[m][n] = sum_k A[m*K+k] * Bw[n*K+k] + bias1[n] + bias2[n]
// ---------------------------------------------------------------------------
__global__ void __launch_bounds__(256) gemm_nt_bias(
    const float* __restrict__ A, const float* __restrict__ Bw,
    const float* __restrict__ bias1, const float* __restrict__ bias2,
    float* __restrict__ C, int M, int N, int K)
{
    __shared__ float As[8][128];
    __shared__ float Bs[8][128];
    const int tid = threadIdx.x;
    const int m0 = blockIdx.y << 7;
    const int n0 = blockIdx.x << 7;
    const int ty = tid >> 4;
    const int tx = tid & 15;

    float acc[8][8];
#pragma unroll
    for (int i = 0; i < 8; i++)
#pragma unroll
        for (int j = 0; j < 8; j++) acc[i][j] = 0.f;

    const int lr = tid >> 1;
    const int lq = (tid & 1) << 2;

    for (int kt = 0; kt < K; kt += 8) {
        float4 va = *(const float4*)&A [(size_t)(m0 + lr) * K + kt + lq];
        float4 vb = *(const float4*)&Bw[(size_t)(n0 + lr) * K + kt + lq];
        As[lq + 0][lr] = va.x; As[lq + 1][lr] = va.y;
        As[lq + 2][lr] = va.z; As[lq + 3][lr] = va.w;
        Bs[lq + 0][lr] = vb.x; Bs[lq + 1][lr] = vb.y;
        Bs[lq + 2][lr] = vb.z; Bs[lq + 3][lr] = vb.w;
        __syncthreads();
#pragma unroll
        for (int kk = 0; kk < 8; kk++) {
            float ra[8], rb[8];
            *(float4*)&ra[0] = *(const float4*)&As[kk][ty * 8];
            *(float4*)&ra[4] = *(const float4*)&As[kk][ty * 8 + 4];
            *(float4*)&rb[0] = *(const float4*)&Bs[kk][tx * 8];
            *(float4*)&rb[4] = *(const float4*)&Bs[kk][tx * 8 + 4];
#pragma unroll
            for (int i = 0; i < 8; i++)
#pragma unroll
                for (int j = 0; j < 8; j++)
                    acc[i][j] = fmaf(ra[i], rb[j], acc[i][j]);
        }
        __syncthreads();
    }

    float bb[8];
#pragma unroll
    for (int j = 0; j < 8; j++)
        bb[j] = bias1[n0 + tx * 8 + j] + bias2[n0 + tx * 8 + j];
#pragma unroll
    for (int i = 0; i < 8; i++) {
        float4 o0 = make_float4(acc[i][0] + bb[0], acc[i][1] + bb[1],
                                acc[i][2] + bb[2], acc[i][3] + bb[3]);
        float4 o1 = make_float4(acc[i][4] + bb[4], acc[i][5] + bb[5],
                                acc[i][6] + bb[6], acc[i][7] + bb[7]);
        size_t row = (size_t)(m0 + ty * 8 + i) * N + n0 + tx * 8;
        *(float4*)&C[row]     = o0;
        *(float4*)&C[row + 4] = o1;
    }
}

// ---------------------------------------------------------------------------
// Persistent LSTM scan. 128 CTAs = 16 groups x 8 ranks, 256 threads.
// W_hh slice in SMEM, k-pair-interleaved for packed fma.rn.f32x2:
//   Wsh float-layout: [(kpair) 0..127][col 0..127 as float2(k even, k odd)]
// h exchange through L2 (double-buffered d_hx), monotonic per-parity
// release/acquire counters instead of atomic RMW spin.
// Dynamic SMEM: Wsh 128KB | hbuf 8KB (2x1024) | red 16KB = 152 KB
// ---------------------------------------------------------------------------
#define SCAN_SMEM ((32768 + 2048 + 4096) * 4)

__global__ void __launch_bounds__(256, 1) lstm_scan(
    const float* __restrict__ Gx, const float* __restrict__ Whh,
    float* __restrict__ h_all, float* __restrict__ h_last)
{
    extern __shared__ float sm[];
    float* Wsh  = sm;                    // [128 kpairs][256 floats]
    float* hbuf = sm + 32768;            // [2][4][256]
    float* red  = hbuf + 2048;           // [8][512]

    const int tid = threadIdx.x;
    const int g   = blockIdx.x >> 3;
    const int r   = blockIdx.x & 7;
    const int j0  = r * JPR;
    const int b0  = g * BPG;

    // ---- load W_hh slice into SMEM, k-pair interleaved ----
    {
        const int c    = tid & 127;             // local col
        const int half = tid >> 7;              // 0/1
        const int gate = c >> 5, jj = c & 31;
        const int gcol = gate * 256 + j0 + jj;
        const float* wrow = Whh + (size_t)gcol * H_ + half * 128;
        float2* W2 = (float2*)Wsh;
#pragma unroll 4
        for (int kk = 0; kk < 128; kk += 4) {
            float4 v = *(const float4*)&wrow[kk];
            int kp = (half * 128 + kk) >> 1;
            W2[(kp + 0) * 128 + c] = make_float2(v.x, v.y);
            W2[(kp + 1) * 128 + c] = make_float2(v.z, v.w);
        }
    }
    for (int i = tid; i < 2048; i += 256) hbuf[i] = 0.f;   // h_{-1} = 0
    __syncthreads();

    const int cg = tid & 31;            // column-pair group
    const int kc = tid >> 5;            // k chunk (32 k = 16 kpairs)
    const int jj = tid & 31;
    float cst = 0.f;

    const float* gxp = (tid < 128)
        ? Gx + ((size_t)(b0 + kc) * T_) * G_ + j0 + jj : Gx;

    // this thread's 4 columns: {2cg, 2cg+1, 64+2cg, 65+2cg}
    const float* wk = Wsh + (kc * 16) * 256 + cg * 4;
    unsigned int* const flag = &d_bar2[0][0];   // indexed per parity below

    for (int t = 0; t < T_; t++) {
        // prefetch gates_x (latency hidden under GEMM)
        float gx0 = 0.f, gx1 = 0.f, gx2 = 0.f, gx3 = 0.f;
        if (tid < 128) {
            const float* gp = gxp + (size_t)t * G_;
            gx0 = __ldg(gp);       gx1 = __ldg(gp + 256);
            gx2 = __ldg(gp + 512); gx3 = __ldg(gp + 768);
        }

        // ---- packed-f32x2 partial GEMM over k chunk kc ----
        unsigned long long acc[4][4];
#pragma unroll
        for (int b = 0; b < 4; b++)
#pragma unroll
            for (int i = 0; i < 4; i++) acc[b][i] = 0ull;

        const float* hp = hbuf + ((t + 1) & 1) * 1024 + kc * 32;
#pragma unroll 16
        for (int kp = 0; kp < 16; kp++) {
            ulonglong2 wa = *(const ulonglong2*)(wk + kp * 256);        // cols 2cg,2cg+1
            ulonglong2 wb = *(const ulonglong2*)(wk + kp * 256 + 128);  // cols 64+2cg,65+2cg
            unsigned long long h0 = *(const unsigned long long*)(hp + 2 * kp);
            unsigned long long h1 = *(const unsigned long long*)(hp + 256 + 2 * kp);
            unsigned long long h2 = *(const unsigned long long*)(hp + 512 + 2 * kp);
            unsigned long long h3 = *(const unsigned long long*)(hp + 768 + 2 * kp);
            fma2(acc[0][0], wa.x, h0); fma2(acc[0][1], wa.y, h0);
            fma2(acc[0][2], wb.x, h0); fma2(acc[0][3], wb.y, h0);
            fma2(acc[1][0], wa.x, h1); fma2(acc[1][1], wa.y, h1);
            fma2(acc[1][2], wb.x, h1); fma2(acc[1][3], wb.y, h1);
            fma2(acc[2][0], wa.x, h2); fma2(acc[2][1], wa.y, h2);
            fma2(acc[2][2], wb.x, h2); fma2(acc[2][3], wb.y, h2);
            fma2(acc[3][0], wa.x, h3); fma2(acc[3][1], wa.y, h3);
            fma2(acc[3][2], wb.x, h3); fma2(acc[3][3], wb.y, h3);
        }
        // epilogue: lo+hi, pairwise STS.64 into red[kc][b][col]
        {
            float2* R2 = (float2*)red;
#pragma unroll
            for (int b = 0; b < 4; b++) {
                float s0 = pair_sum(acc[b][0]);
                float s1 = pair_sum(acc[b][1]);
                float s2 = pair_sum(acc[b][2]);
                float s3 = pair_sum(acc[b][3]);
                R2[kc * 256 + b * 64 + cg]      = make_float2(s0, s1);
                R2[kc * 256 + b * 64 + 32 + cg] = make_float2(s2, s3);
            }
        }
        __syncthreads();

        // ---- fused reduce + activation + h store (128 threads) ----
        if (tid < 128) {
            const int base = kc * 128 + jj;   // kc == batch here
            float s0 = 0.f, s1 = 0.f, s2 = 0.f, s3 = 0.f;
#pragma unroll
            for (int p = 0; p < 8; p++) {
                s0 += red[p * 512 + base];
                s1 += red[p * 512 + base + 32];
                s2 += red[p * 512 + base + 64];
                s3 += red[p * 512 + base + 96];
            }
            float iv = sigmf(s0 + gx0);
            float fv = sigmf(s1 + gx1);
            float gv = tanhff(s2 + gx2);
            float ov = sigmf(s3 + gx3);
            cst = fv * cst + iv * gv;
            float hv = ov * tanhff(cst);

            const int gb = b0 + kc, j = j0 + jj;
            if (t < T_ - 1) d_hx[t & 1][gb * H_ + j] = hv;
            if (h_all)  h_all[((size_t)gb * T_ + t) * H_ + j] = hv;
            if (h_last && t == T_ - 1) h_last[gb * H_ + j] = hv;
        }
        __syncthreads();   // all h stores done before flag release
        if (t == T_ - 1) break;

        // ---- group barrier: release-red, acquire-poll (all threads) ----
        {
            unsigned int* fp = &d_bar2[t & 1][g];
            if (tid == 0)
                asm volatile("red.release.gpu.global.add.u32 [%0], 1;"
                             :: "l"(fp) : "memory");
            const unsigned int target = (unsigned int)RPG * ((t >> 1) + 1);
            unsigned int v;
            do {
                asm volatile("ld.acquire.gpu.global.u32 %0, [%1];"
                             : "=r"(v) : "l"(fp) : "memory");
            } while (v < target);
        }
        // ---- reload full group h (4KB, one float4 per thread) ----
        {
            const float4* src = (const float4*)(&d_hx[t & 1][b0 * H_]);
            ((float4*)(hbuf + (t & 1) * 1024))[tid] = __ldcg(src + tid);
        }
        __syncthreads();
    }

    // ---- reset counters so the next launch / graph replay starts clean ----
    if (tid == 0) {
        __threadfence();
        atomicAdd(&d_done[g], 1);
        if (r == 0) {
            while (atomicAdd(&d_done[g], 0) < RPG) { }
            d_bar2[0][g] = 0;
            d_bar2[1][g] = 0;
            d_done[g]    = 0;
            __threadfence();
        }
    }
}

// ---------------------------------------------------------------------------
// Head: logits = h_last @ fc_w^T + fc_b ; softmax rows. One block.
// ---------------------------------------------------------------------------
__global__ void __launch_bounds__(192) head_kernel(
    const float* __restrict__ hl, const float* __restrict__ fw,
    const float* __restrict__ fb, float* __restrict__ out)
{
    __shared__ float lg[B_ * C_];
    const int tid = threadIdx.x;
    if (tid < B_ * C_) {
        const int b = tid / C_, c = tid % C_;
        float s = fb[c];
        const float* hr = hl + b * H_;
        const float* wr = fw + c * H_;
#pragma unroll 8
        for (int j = 0; j < H_; j++) s = fmaf(hr[j], wr[j], s);
        lg[tid] = s;
    }
    __syncthreads();
    if (tid < B_) {
        float a = lg[tid * 3], b2 = lg[tid * 3 + 1], c2 = lg[tid * 3 + 2];
        float m = fmaxf(a, fmaxf(b2, c2));
        float e0 = expf(a - m), e1 = expf(b2 - m), e2 = expf(c2 - m);
        float inv = 1.f / (e0 + e1 + e2);
        out[tid * 3]     = e0 * inv;
        out[tid * 3 + 1] = e1 * inv;
        out[tid * 3 + 2] = e2 * inv;
    }
}

// ---------------------------------------------------------------------------
extern "C" void kernel_launch(void* const* d_in, const int* in_sizes, int n_in,
                              void* d_out, int out_size)
{
    const float* x    = (const float*)d_in[0];
    const float* Wih0 = (const float*)d_in[1];
    const float* Whh0 = (const float*)d_in[2];
    const float* bih0 = (const float*)d_in[3];
    const float* bhh0 = (const float*)d_in[4];
    const float* Wih1 = (const float*)d_in[5];
    const float* Whh1 = (const float*)d_in[6];
    const float* bih1 = (const float*)d_in[7];
    const float* bhh1 = (const float*)d_in[8];
    const float* fw   = (const float*)d_in[9];
    const float* fb   = (const float*)d_in[10];
    float* out = (float*)d_out;

    float *G0, *G1, *H0, *HL;
    cudaGetSymbolAddress((void**)&G0, d_G0);
    cudaGetSymbolAddress((void**)&G1, d_G1);
    cudaGetSymbolAddress((void**)&H0, d_H0);
    cudaGetSymbolAddress((void**)&HL, d_HL);

    cudaFuncSetAttribute(lstm_scan, cudaFuncAttributeMaxDynamicSharedMemorySize,
                         SCAN_SMEM);

    const int M = B_ * T_;
    dim3 ggrid(G_ / 128, M / 128);

    // layer 0: gates_x0 = x @ W_ih_0^T + b
    gemm_nt_bias<<<ggrid, 256>>>(x, Wih0, bih0, bhh0, G0, M, G_, I_);
    // layer 0 recurrence -> full h0
    lstm_scan<<<NGROUP * RPG, 256, SCAN_SMEM>>>(G0, Whh0, H0, nullptr);
    // layer 1: gates_x1 = h0 @ W_ih_1^T + b
    gemm_nt_bias<<<ggrid, 256>>>(H0, Wih1, bih1, bhh1, G1, M, G_, H_);
    // layer 1 recurrence -> last h only
    lstm_scan<<<NGROUP * RPG, 256, SCAN_SMEM>>>(G1, Whh1, nullptr, HL);
    // FC + softmax
    head_kernel<<<1, 192>>>(HL, fw, fb, out);
}